// round 1
// baseline (speedup 1.0000x reference)
#include <cuda_runtime.h>
#include <math.h>

#define NB 8
#define NT 8192
#define ND 128
#define NH 8
#define DHD 16
#define TILE 128
#define SROW 129   // smem row stride (floats) for 128-wide tiles, conflict-free

// Scratch: per-(b,h) context matrices and k-sums. Device globals (no allocs allowed).
static __device__ float g_ctx[NB * NH * DHD * DHD];   // [b][h][d][e]
static __device__ float g_ksum[NB * NH * DHD];        // [b][h][d]

// ---------------------------------------------------------------------------
// 128x128x128 fp32 GEMM: out = A_s(128x128, smem, stride SROW) @ W(global) + bias.
// 256 threads, 8x8 register microtile per thread, K streamed in 16-chunks.
// Epilogue to smem (stride SROW) or to global (stride 128).
// ---------------------------------------------------------------------------
__device__ __forceinline__ void gemm128(
    const float* __restrict__ A_s,
    const float* __restrict__ W,
    const float* __restrict__ bias,
    float* __restrict__ w_s,          // [16][128] smem scratch
    float* out_s,                     // smem out (or nullptr)
    float* out_g,                     // global out (or nullptr)
    int tid)
{
    const int tx = tid & 15;
    const int ty = tid >> 4;

    float acc[8][8];
    {
        float bj[8];
        #pragma unroll
        for (int j = 0; j < 8; j++) bj[j] = bias[tx * 8 + j];
        #pragma unroll
        for (int i = 0; i < 8; i++)
            #pragma unroll
            for (int j = 0; j < 8; j++) acc[i][j] = bj[j];
    }

    for (int kk = 0; kk < 128; kk += 16) {
        __syncthreads();   // protect w_s reuse (and A_s load before first iter)
        #pragma unroll
        for (int l = 0; l < 2; l++) {
            int idx = tid + l * 256;          // 512 float4 total
            int r = idx >> 5, c4 = idx & 31;
            ((float4*)(w_s + r * 128))[c4] =
                ((const float4*)(W + (size_t)(kk + r) * 128))[c4];
        }
        __syncthreads();
        #pragma unroll
        for (int p = 0; p < 16; p++) {
            float a[8];
            #pragma unroll
            for (int i = 0; i < 8; i++)
                a[i] = A_s[(ty * 8 + i) * SROW + kk + p];
            float4 b0 = ((const float4*)(w_s + p * 128))[tx * 2];
            float4 b1 = ((const float4*)(w_s + p * 128))[tx * 2 + 1];
            float bb[8] = {b0.x, b0.y, b0.z, b0.w, b1.x, b1.y, b1.z, b1.w};
            #pragma unroll
            for (int i = 0; i < 8; i++)
                #pragma unroll
                for (int j = 0; j < 8; j++)
                    acc[i][j] = fmaf(a[i], bb[j], acc[i][j]);
        }
    }
    __syncthreads();

    if (out_s) {
        #pragma unroll
        for (int i = 0; i < 8; i++)
            #pragma unroll
            for (int j = 0; j < 8; j++)
                out_s[(ty * 8 + i) * SROW + tx * 8 + j] = acc[i][j];
    } else {
        #pragma unroll
        for (int i = 0; i < 8; i++) {
            float4 s0 = make_float4(acc[i][0], acc[i][1], acc[i][2], acc[i][3]);
            float4 s1 = make_float4(acc[i][4], acc[i][5], acc[i][6], acc[i][7]);
            float4* dst = (float4*)(out_g + (size_t)(ty * 8 + i) * 128 + tx * 8);
            dst[0] = s0;
            dst[1] = s1;
        }
    }
}

// RoPE (per head, Dh=16) + elu(.)+1, in place on a [128][SROW] smem tile.
__device__ __forceinline__ void rope_elu(float* s, int t0, int tid)
{
    // 10000^(-j/8) = 10^(-j/2), correctly rounded fp32
    const float invf[8] = {1.0f, 0.31622776601683794f, 0.1f, 0.03162277660168379f,
                           0.01f, 0.0031622776601683794f, 0.001f,
                           0.00031622776601683794f};
    for (int task = tid; task < TILE * NH; task += 256) {
        int r = task >> 3;
        int h = task & 7;
        float* p = s + r * SROW + h * DHD;
        float tf = (float)(t0 + r);
        #pragma unroll
        for (int j = 0; j < 8; j++) {
            float f = tf * invf[j];
            float sn, cs;
            sincosf(f, &sn, &cs);
            float x1 = p[j], x2 = p[j + 8];
            float y1 = x1 * cs - x2 * sn;
            float y2 = x1 * sn + x2 * cs;
            p[j]     = (y1 > 0.f) ? (y1 + 1.f) : expf(y1);
            p[j + 8] = (y2 > 0.f) ? (y2 + 1.f) : expf(y2);
        }
    }
}

// ---------------------------------------------------------------------------
// Pass 0: zero scratch (graph replays must start clean).
// ---------------------------------------------------------------------------
extern "C" __global__ void la_zero_scratch()
{
    int i = blockIdx.x * blockDim.x + threadIdx.x;
    if (i < NB * NH * DHD * DHD) g_ctx[i] = 0.f;
    if (i < NB * NH * DHD)       g_ksum[i] = 0.f;
}

// ---------------------------------------------------------------------------
// Pass 1: k = rope_elu(x@Wk+bk), v = x@Wv+bv; accumulate ctx += k⊗v, ksum += k.
// Grid: (T/128, B), 256 threads.
// ---------------------------------------------------------------------------
extern "C" __global__ void __launch_bounds__(256, 1)
la_kv_ctx_kernel(const float* __restrict__ x,
                 const float* __restrict__ Wk, const float* __restrict__ bk,
                 const float* __restrict__ Wv, const float* __restrict__ bv)
{
    extern __shared__ float sm[];
    float* x_s = sm;                       // [128][SROW]
    float* k_s = x_s + TILE * SROW;        // [128][SROW]
    float* v_s = k_s + TILE * SROW;        // [128][SROW]
    float* w_s = v_s + TILE * SROW;        // [16][128]

    const int b = blockIdx.y;
    const int t0 = blockIdx.x * TILE;
    const int tid = threadIdx.x;
    const float* xp = x + ((size_t)b * NT + t0) * ND;

    for (int i = tid; i < TILE * ND / 4; i += 256) {
        int r = i >> 5, c4 = i & 31;
        float4 v4 = ((const float4*)xp)[i];
        float* d = x_s + r * SROW + c4 * 4;
        d[0] = v4.x; d[1] = v4.y; d[2] = v4.z; d[3] = v4.w;
    }
    // first __syncthreads inside gemm128 covers the x_s load

    for (int g = 0; g < 2; g++) {
        gemm128(x_s, g ? Wv : Wk, g ? bv : bk, w_s,
                g ? v_s : k_s, (float*)0, tid);
    }
    __syncthreads();
    rope_elu(k_s, t0, tid);
    __syncthreads();

    // Per-tile partial ctx: thread (d,e) covers all 8 heads.
    const int d = tid >> 4;     // 0..15
    const int e = tid & 15;     // 0..15
    float part[NH];
    #pragma unroll
    for (int h = 0; h < NH; h++) part[h] = 0.f;
    for (int t = 0; t < TILE; t++) {
        const float* kr = k_s + t * SROW;
        const float* vr = v_s + t * SROW;
        #pragma unroll
        for (int h = 0; h < NH; h++)
            part[h] = fmaf(kr[h * DHD + d], vr[h * DHD + e], part[h]);
    }
    float* ctxb = g_ctx + (size_t)b * NH * DHD * DHD;
    #pragma unroll
    for (int h = 0; h < NH; h++)
        atomicAdd(ctxb + h * DHD * DHD + d * DHD + e, part[h]);

    if (tid < ND) {
        float s = 0.f;
        for (int t = 0; t < TILE; t++) s += k_s[t * SROW + tid];
        atomicAdd(g_ksum + (size_t)b * ND + tid, s);
    }
}

// ---------------------------------------------------------------------------
// Pass 2: q = rope_elu(x@Wq+bq); out = ((q@ctx) * z) @ Wo + bo.
// ---------------------------------------------------------------------------
extern "C" __global__ void __launch_bounds__(256, 1)
la_q_attn_out_kernel(const float* __restrict__ x,
                     const float* __restrict__ Wq, const float* __restrict__ bq,
                     const float* __restrict__ Wo, const float* __restrict__ bo,
                     float* __restrict__ out)
{
    extern __shared__ float sm[];
    float* x_s   = sm;                       // [128][SROW], reused as attn buffer
    float* q_s   = x_s + TILE * SROW;        // [128][SROW]
    float* w_s   = q_s + TILE * SROW;        // [16][128]
    float* ctx_s = w_s + 16 * 128;           // [8][16][16]
    float* ksum_s = ctx_s + NH * DHD * DHD;  // [128]

    const int b = blockIdx.y;
    const int t0 = blockIdx.x * TILE;
    const int tid = threadIdx.x;
    const float* xp = x + ((size_t)b * NT + t0) * ND;

    for (int i = tid; i < TILE * ND / 4; i += 256) {
        int r = i >> 5, c4 = i & 31;
        float4 v4 = ((const float4*)xp)[i];
        float* dd = x_s + r * SROW + c4 * 4;
        dd[0] = v4.x; dd[1] = v4.y; dd[2] = v4.z; dd[3] = v4.w;
    }
    for (int i = tid; i < NH * DHD * DHD; i += 256)
        ctx_s[i] = g_ctx[(size_t)b * NH * DHD * DHD + i];
    if (tid < ND) ksum_s[tid] = g_ksum[(size_t)b * ND + tid];

    gemm128(x_s, Wq, bq, w_s, q_s, (float*)0, tid);
    __syncthreads();
    rope_elu(q_s, t0, tid);
    __syncthreads();

    // Attention apply: warp h handles head h, 4 rows per lane.
    const int lane = tid & 31;
    const int h = tid >> 5;
    for (int i = 0; i < 4; i++) {
        int t = i * 32 + lane;
        const float* qr = q_s + t * SROW + h * DHD;
        float z = 1e-6f;
        #pragma unroll
        for (int d2 = 0; d2 < DHD; d2++)
            z = fmaf(qr[d2], ksum_s[h * DHD + d2], z);
        float o[DHD];
        #pragma unroll
        for (int e = 0; e < DHD; e++) o[e] = 0.f;
        #pragma unroll
        for (int d2 = 0; d2 < DHD; d2++) {
            float qv = qr[d2];
            const float* cr = ctx_s + h * DHD * DHD + d2 * DHD;
            #pragma unroll
            for (int e = 0; e < DHD; e++)
                o[e] = fmaf(qv, cr[e], o[e]);
        }
        float zi = 1.f / z;
        float* ar = x_s + t * SROW + h * DHD;   // x_s reused as attn buffer
        #pragma unroll
        for (int e = 0; e < DHD; e++) ar[e] = o[e] * zi;
    }
    __syncthreads();

    gemm128(x_s, Wo, bo, w_s, (float*)0,
            out + ((size_t)b * NT + t0) * ND, tid);
}

// ---------------------------------------------------------------------------
extern "C" void kernel_launch(void* const* d_in, const int* in_sizes, int n_in,
                              void* d_out, int out_size)
{
    const float* x  = (const float*)d_in[0];
    const float* Wq = (const float*)d_in[1];
    const float* bq = (const float*)d_in[2];
    const float* Wk = (const float*)d_in[3];
    const float* bk = (const float*)d_in[4];
    const float* Wv = (const float*)d_in[5];
    const float* bv = (const float*)d_in[6];
    const float* Wo = (const float*)d_in[7];
    const float* bo = (const float*)d_in[8];
    float* out = (float*)d_out;

    const size_t smemA = (size_t)(3 * TILE * SROW + 16 * 128) * sizeof(float);
    const size_t smemB = (size_t)(2 * TILE * SROW + 16 * 128 +
                                  NH * DHD * DHD + ND) * sizeof(float);
    cudaFuncSetAttribute(la_kv_ctx_kernel,
                         cudaFuncAttributeMaxDynamicSharedMemorySize, (int)smemA);
    cudaFuncSetAttribute(la_q_attn_out_kernel,
                         cudaFuncAttributeMaxDynamicSharedMemorySize, (int)smemB);

    la_zero_scratch<<<(NB * NH * DHD * DHD + 255) / 256, 256>>>();

    dim3 grid(NT / TILE, NB);
    la_kv_ctx_kernel<<<grid, 256, smemA>>>(x, Wk, bk, Wv, bv);
    la_q_attn_out_kernel<<<grid, 256, smemB>>>(x, Wq, bq, Wo, bo, out);
}